// round 6
// baseline (speedup 1.0000x reference)
#include <cuda_runtime.h>
#include <cstdint>

// ---------------------------------------------------------------------------
// Swin shifted-window attention. B=32, 64x64, C=256, 8 heads x 32, ws=8, shift=4.
// k_round: pre-round w_qkv, w_out to tf32 (RNA)          (~1 MB, ~5 us)
// k_qkv  : qkv = gather(x) @ w_qkv^T + b ; A staged LDG+cvt+STS, B cp.async,
//          3-stage ring, 1 sync per K-chunk, ldmatrix + mma tf32
// k_attn : per (window,head) attention, bias+mask+softmax, writes rounded o
// k_out  : out = o @ w_out^T + b, 3-stage cp.async ring, inverse-roll scatter
// ---------------------------------------------------------------------------

#define SCALE_F 0.1767766952966369f
#define ABYTES  18432               // 128*36*4 (one operand, one stage)
#define STAGE   36864               // A+B one stage

__device__ float g_wqkv[196608];    // rounded w_qkv
__device__ float g_wout[65536];     // rounded w_out
__device__ float g_q[33554432];     // [win][head][tok 64][d 32]
__device__ float g_k[33554432];     // [win][head][tok 64][d 32]
__device__ float g_v[33554432];     // [win][head][d 32][tok 64]  (transposed)
__device__ float g_o[33554432];     // [token 131072][256] rounded

__device__ __forceinline__ float tf32f(float f) {
    uint32_t u;
    asm("cvt.rna.tf32.f32 %0, %1;" : "=r"(u) : "f"(f));
    return __uint_as_float(u);
}
__device__ __forceinline__ uint32_t smem_u32(const void* p) {
    return (uint32_t)__cvta_generic_to_shared(p);
}
__device__ __forceinline__ void cp16(uint32_t s, const void* g) {
    asm volatile("cp.async.cg.shared.global [%0], [%1], 16;" :: "r"(s), "l"(g));
}
__device__ __forceinline__ void cp_commit() {
    asm volatile("cp.async.commit_group;");
}
template <int N> __device__ __forceinline__ void cp_wait() {
    asm volatile("cp.async.wait_group %0;" :: "n"(N));
}
__device__ __forceinline__ void ldsm4(uint32_t* r, uint32_t a) {
    asm volatile("ldmatrix.sync.aligned.m8n8.x4.shared.b16 {%0,%1,%2,%3}, [%4];"
                 : "=r"(r[0]), "=r"(r[1]), "=r"(r[2]), "=r"(r[3]) : "r"(a));
}
__device__ __forceinline__ void mma8(float* c, const uint32_t* a,
                                     uint32_t b0, uint32_t b1) {
    asm volatile("mma.sync.aligned.m16n8k8.row.col.f32.tf32.tf32.f32 "
                 "{%0,%1,%2,%3},{%4,%5,%6,%7},{%8,%9},{%0,%1,%2,%3};\n"
                 : "+f"(c[0]), "+f"(c[1]), "+f"(c[2]), "+f"(c[3])
                 : "r"(a[0]), "r"(a[1]), "r"(a[2]), "r"(a[3]), "r"(b0), "r"(b1));
}

// window-token m -> source row in (B,64,64), cyclic shift by 4 (self-inverse map)
__device__ __forceinline__ int token_src(int m) {
    int w = m >> 6, p = m & 63;
    int b = w >> 6, widx = w & 63;
    int y = (((widx >> 3) << 3) + (p >> 3) + 4) & 63;
    int x = (((widx & 7) << 3) + (p & 7) + 4) & 63;
    return (b << 12) | (y << 6) | x;
}

// ---------------------------------------------------------------------------
__global__ void k_round(const float* __restrict__ wq, const float* __restrict__ wo) {
    const int NQ = 196608 / 4, NO = 65536 / 4;
    int i = blockIdx.x * blockDim.x + threadIdx.x;
    if (i < NQ + NO) {
        const float4* s;
        float4* d;
        if (i < NQ) { s = (const float4*)wq + i;        d = (float4*)g_wqkv + i; }
        else        { s = (const float4*)wo + (i - NQ); d = (float4*)g_wout + (i - NQ); }
        float4 v = __ldg(s);
        v.x = tf32f(v.x); v.y = tf32f(v.y); v.z = tf32f(v.z); v.w = tf32f(v.w);
        *d = v;
    }
}

// ---------------------------------------------------------------------------
// K1: qkv GEMM. CTA 128(M) x 128(N), K=256 in 8 chunks of 32.
// 3-stage ring: A via LDG(x)+cvt+STS, B via cp.async. One sync per chunk.
// 8 warps: 2(M,64) x 4(N,32). Epilogue scatters rounded q/k/v.
// ---------------------------------------------------------------------------
__global__ void __launch_bounds__(256, 2)
k_qkv(const float* __restrict__ x, const float* __restrict__ bqkv) {
    extern __shared__ float smf[];
    const int t = threadIdx.x;
    const int mbase = blockIdx.y << 7;
    const int nbase = blockIdx.x << 7;
    const int lane = t & 31, wid = t >> 5;
    const int g = lane >> 2, tg = lane & 3;
    const int wm = (wid & 1) << 6;
    const int wn = (wid >> 1) << 5;

    const uint32_t sbase = smem_u32(smf);
    const int srow = t >> 1, scol = (t & 1) << 4;
    const float* gA = x + (size_t)token_src(mbase + srow) * 256 + scol;
    const float* gB = g_wqkv + (size_t)(nbase + srow) * 256 + scol;
    const uint32_t offA = (srow * 36 + scol) * 4;   // byte offset within stage
    const uint32_t offB = offA + ABYTES;

    const int tt = lane >> 3, rr = lane & 7;
    const uint32_t aoff = (((tt & 1) * 8 + rr) * 36 + (tt >> 1) * 4) * 4;
    const uint32_t boff = (((tt >> 1) * 8 + rr) * 36 + (tt & 1) * 4) * 4;

    float acc[4][4][4] = {};

    // prologue: stages 0,1
#pragma unroll
    for (int s = 0; s < 2; ++s) {
#pragma unroll
        for (int j = 0; j < 4; ++j) {
            float4 v = __ldg((const float4*)(gA + s * 32 + j * 4));
            v.x = tf32f(v.x); v.y = tf32f(v.y); v.z = tf32f(v.z); v.w = tf32f(v.w);
            *(float4*)((char*)smf + s * STAGE + offA + j * 16) = v;
        }
#pragma unroll
        for (int j = 0; j < 4; ++j)
            cp16(sbase + s * STAGE + offB + j * 16, gB + s * 32 + j * 4);
        cp_commit();
    }

    for (int kc = 0; kc < 8; ++kc) {
        if (kc == 7) cp_wait<0>(); else cp_wait<1>();
        __syncthreads();

        if (kc < 6) {  // issue stage kc+2 (buffer (kc+2)%3 drained by barrier above)
            const int s = kc + 2;
            const uint32_t sb = (uint32_t)(s % 3) * STAGE;
#pragma unroll
            for (int j = 0; j < 4; ++j) {
                float4 v = __ldg((const float4*)(gA + s * 32 + j * 4));
                v.x = tf32f(v.x); v.y = tf32f(v.y); v.z = tf32f(v.z); v.w = tf32f(v.w);
                *(float4*)((char*)smf + sb + offA + j * 16) = v;
            }
#pragma unroll
            for (int j = 0; j < 4; ++j)
                cp16(sbase + sb + offB + j * 16, gB + s * 32 + j * 4);
            cp_commit();
        }

        const uint32_t base = sbase + (uint32_t)(kc % 3) * STAGE;
#pragma unroll
        for (int k8 = 0; k8 < 4; ++k8) {
            uint32_t af[4][4];
#pragma unroll
            for (int mt = 0; mt < 4; ++mt)
                ldsm4(af[mt], base + (wm + mt * 16) * 144 + aoff + k8 * 32);
            uint32_t bf[2][4];
#pragma unroll
            for (int bt = 0; bt < 2; ++bt)
                ldsm4(bf[bt], base + ABYTES + (wn + bt * 16) * 144 + boff + k8 * 32);
#pragma unroll
            for (int mt = 0; mt < 4; ++mt) {
                mma8(acc[mt][0], af[mt], bf[0][0], bf[0][1]);
                mma8(acc[mt][1], af[mt], bf[0][2], bf[0][3]);
                mma8(acc[mt][2], af[mt], bf[1][0], bf[1][1]);
                mma8(acc[mt][3], af[mt], bf[1][2], bf[1][3]);
            }
        }
    }

    const int which = nbase >> 8;  // uniform per CTA: 0=q, 1=k, 2=v
#pragma unroll
    for (int mt = 0; mt < 4; ++mt) {
#pragma unroll
        for (int half = 0; half < 2; ++half) {
            int m = mbase + wm + mt * 16 + g + half * 8;
            int w = m >> 6, p = m & 63;
#pragma unroll
            for (int nt = 0; nt < 4; ++nt) {
                int n0 = nbase + wn + nt * 8 + tg * 2;
                int h = (n0 >> 5) & 7, d = n0 & 31;
                int wh = (w << 3) + h;
                float v0 = tf32f(acc[mt][nt][half * 2 + 0] + __ldg(bqkv + n0));
                float v1 = tf32f(acc[mt][nt][half * 2 + 1] + __ldg(bqkv + n0 + 1));
                if (which == 0) {
                    *(float2*)(g_q + ((wh << 6) + p) * 32 + d) = make_float2(v0, v1);
                } else if (which == 1) {
                    *(float2*)(g_k + ((wh << 6) + p) * 32 + d) = make_float2(v0, v1);
                } else {
                    g_v[(((wh << 5) + d) << 6) + p] = v0;
                    g_v[(((wh << 5) + d + 1) << 6) + p] = v1;
                }
            }
        }
    }
}

// ---------------------------------------------------------------------------
// K2: attention per (window, head). 4 warps, each owns 16 full S rows.
// ---------------------------------------------------------------------------
__global__ void __launch_bounds__(128)
k_attn(const float* __restrict__ pos_enc) {
    __shared__ float qs[64 * 36];
    __shared__ float ks[64 * 36];
    __shared__ float vs[32 * 68];
    __shared__ float ps[64 * 68];
    __shared__ float pos_s[232];

    const int t = threadIdx.x;
    const int bh = blockIdx.x;
    const int w = bh >> 3, h = bh & 7;
    const int wh = (w << 3) + h;

    {
        int row = t >> 1, col = (t & 1) << 4;
        const float* q = g_q + ((size_t)(wh << 6) + row) * 32 + col;
        const float* k = g_k + ((size_t)(wh << 6) + row) * 32 + col;
        uint32_t dq = smem_u32(qs) + (row * 36 + col) * 4;
        uint32_t dk = smem_u32(ks) + (row * 36 + col) * 4;
#pragma unroll
        for (int j = 0; j < 4; ++j) { cp16(dq + j * 16, q + j * 4); cp16(dk + j * 16, k + j * 4); }
        int vr = t >> 2, vc = (t & 3) << 4;
        const float* v = g_v + ((size_t)(wh << 5) + vr) * 64 + vc;
        uint32_t dv = smem_u32(vs) + (vr * 68 + vc) * 4;
#pragma unroll
        for (int j = 0; j < 4; ++j) { cp16(dv + j * 16, v + j * 4); }
        cp_commit();
    }
    for (int i = t; i < 225; i += 128) pos_s[i] = __ldg(pos_enc + h * 225 + i);
    cp_wait<0>();
    __syncthreads();

    const int lane = t & 31, wid = t >> 5;
    const int g = lane >> 2, tg = lane & 3;
    const int wb = wid << 4;
    const int tt = lane >> 3, rr = lane & 7;
    const uint32_t aoff36 = (((tt & 1) * 8 + rr) * 36 + (tt >> 1) * 4) * 4;
    const uint32_t boff36 = (((tt >> 1) * 8 + rr) * 36 + (tt & 1) * 4) * 4;
    const uint32_t aoff68 = (((tt & 1) * 8 + rr) * 68 + (tt >> 1) * 4) * 4;
    const uint32_t boff68 = (((tt >> 1) * 8 + rr) * 68 + (tt & 1) * 4) * 4;

    // S = q k^T
    float sacc[8][4] = {};
    const uint32_t qb = smem_u32(qs) + wb * 144 + aoff36;
    const uint32_t kb = smem_u32(ks) + boff36;
#pragma unroll
    for (int k8 = 0; k8 < 4; ++k8) {
        uint32_t af[4];
        ldsm4(af, qb + k8 * 32);
        uint32_t bf[4][4];
#pragma unroll
        for (int bt = 0; bt < 4; ++bt)
            ldsm4(bf[bt], kb + bt * 16 * 144 + k8 * 32);
#pragma unroll
        for (int nt = 0; nt < 8; ++nt)
            mma8(sacc[nt], af, bf[nt >> 1][(nt & 1) * 2], bf[nt >> 1][(nt & 1) * 2 + 1]);
    }

    // bias + shift mask + softmax
    const int widx = w & 63;
    const int my = ((widx >> 3) == 7);
    const int mxw = ((widx & 7) == 7);
    auto regf = [&](int py, int px) {
        int ry = my ? (py < 4 ? 1 : 2) : 0;
        int rx = mxw ? (px < 4 ? 1 : 2) : 0;
        return ry * 3 + rx;
    };
    const int iL = wb + g, iH = iL + 8;
    const int pyL = iL >> 3, pxL = iL & 7;
    const int pyH = iH >> 3, pxH = iH & 7;
    const int regL = regf(pyL, pxL), regH = regf(pyH, pxH);

    float mL = -1e30f, mH = -1e30f;
#pragma unroll
    for (int nt = 0; nt < 8; ++nt) {
#pragma unroll
        for (int jj = 0; jj < 2; ++jj) {
            int j = (nt << 3) + (tg << 1) + jj;
            int pyj = j >> 3, pxj = j & 7;
            int regj = regf(pyj, pxj);
            float sL = sacc[nt][jj] * SCALE_F + pos_s[(pyL - pyj + 7) * 15 + (pxL - pxj + 7)];
            float sH = sacc[nt][2 + jj] * SCALE_F + pos_s[(pyH - pyj + 7) * 15 + (pxH - pxj + 7)];
            if (regj != regL) sL = -1e30f;
            if (regj != regH) sH = -1e30f;
            sacc[nt][jj] = sL;
            sacc[nt][2 + jj] = sH;
            mL = fmaxf(mL, sL);
            mH = fmaxf(mH, sH);
        }
    }
    mL = fmaxf(mL, __shfl_xor_sync(0xffffffffu, mL, 1));
    mL = fmaxf(mL, __shfl_xor_sync(0xffffffffu, mL, 2));
    mH = fmaxf(mH, __shfl_xor_sync(0xffffffffu, mH, 1));
    mH = fmaxf(mH, __shfl_xor_sync(0xffffffffu, mH, 2));

    float sumL = 0.f, sumH = 0.f;
#pragma unroll
    for (int nt = 0; nt < 8; ++nt) {
#pragma unroll
        for (int jj = 0; jj < 2; ++jj) {
            int j = (nt << 3) + (tg << 1) + jj;
            float eL = tf32f(__expf(sacc[nt][jj] - mL));
            float eH = tf32f(__expf(sacc[nt][2 + jj] - mH));
            sumL += eL;
            sumH += eH;
            ps[iL * 68 + j] = eL;
            ps[iH * 68 + j] = eH;
        }
    }
    sumL += __shfl_xor_sync(0xffffffffu, sumL, 1);
    sumL += __shfl_xor_sync(0xffffffffu, sumL, 2);
    sumH += __shfl_xor_sync(0xffffffffu, sumH, 1);
    sumH += __shfl_xor_sync(0xffffffffu, sumH, 2);
    const float invL = 1.f / sumL, invH = 1.f / sumH;
    __syncwarp();

    // O = P V
    float oacc[4][4] = {};
    const uint32_t pb = smem_u32(ps) + wb * 272 + aoff68;
    const uint32_t vb = smem_u32(vs) + boff68;
#pragma unroll
    for (int k8 = 0; k8 < 8; ++k8) {
        uint32_t pf[4];
        ldsm4(pf, pb + k8 * 32);
        uint32_t vf[2][4];
#pragma unroll
        for (int bt = 0; bt < 2; ++bt)
            ldsm4(vf[bt], vb + bt * 16 * 272 + k8 * 32);
#pragma unroll
        for (int nt = 0; nt < 4; ++nt)
            mma8(oacc[nt], pf, vf[nt >> 1][(nt & 1) * 2], vf[nt >> 1][(nt & 1) * 2 + 1]);
    }

    float* ob = g_o + (size_t)(w << 6) * 256 + (h << 5);
#pragma unroll
    for (int nt = 0; nt < 4; ++nt) {
        int d = (nt << 3) + (tg << 1);
        *(float2*)(ob + (size_t)iL * 256 + d) =
            make_float2(tf32f(oacc[nt][0] * invL), tf32f(oacc[nt][1] * invL));
        *(float2*)(ob + (size_t)iH * 256 + d) =
            make_float2(tf32f(oacc[nt][2] * invH), tf32f(oacc[nt][3] * invH));
    }
}

// ---------------------------------------------------------------------------
// K3: out = o @ w_out^T + b_out, 3-stage cp.async ring, inverse-roll scatter.
// ---------------------------------------------------------------------------
__global__ void __launch_bounds__(256, 2)
k_out(const float* __restrict__ bout, float* __restrict__ out) {
    extern __shared__ float smf[];
    const int t = threadIdx.x;
    const int mbase = blockIdx.y << 7;
    const int nbase = blockIdx.x << 7;
    const int lane = t & 31, wid = t >> 5;
    const int g = lane >> 2, tg = lane & 3;
    const int wm = (wid & 1) << 6;
    const int wn = (wid >> 1) << 5;

    const uint32_t sbase = smem_u32(smf);
    const int srow = t >> 1, scol = (t & 1) << 4;
    const float* gA = g_o + (size_t)(mbase + srow) * 256 + scol;
    const float* gB = g_wout + (size_t)(nbase + srow) * 256 + scol;
    const uint32_t offA = (srow * 36 + scol) * 4;
    const uint32_t offB = offA + ABYTES;

    const int tt = lane >> 3, rr = lane & 7;
    const uint32_t aoff = (((tt & 1) * 8 + rr) * 36 + (tt >> 1) * 4) * 4;
    const uint32_t boff = (((tt >> 1) * 8 + rr) * 36 + (tt & 1) * 4) * 4;

    float acc[4][4][4] = {};

#pragma unroll
    for (int s = 0; s < 2; ++s) {
        const uint32_t sb = sbase + s * STAGE;
#pragma unroll
        for (int j = 0; j < 4; ++j) {
            cp16(sb + offA + j * 16, gA + s * 32 + j * 4);
            cp16(sb + offB + j * 16, gB + s * 32 + j * 4);
        }
        cp_commit();
    }

    for (int kc = 0; kc < 8; ++kc) {
        if (kc == 7) cp_wait<0>(); else cp_wait<1>();
        __syncthreads();

        if (kc < 6) {
            const int s = kc + 2;
            const uint32_t sb = sbase + (uint32_t)(s % 3) * STAGE;
#pragma unroll
            for (int j = 0; j < 4; ++j) {
                cp16(sb + offA + j * 16, gA + s * 32 + j * 4);
                cp16(sb + offB + j * 16, gB + s * 32 + j * 4);
            }
            cp_commit();
        }

        const uint32_t base = sbase + (uint32_t)(kc % 3) * STAGE;
#pragma unroll
        for (int k8 = 0; k8 < 4; ++k8) {
            uint32_t af[4][4];
#pragma unroll
            for (int mt = 0; mt < 4; ++mt)
                ldsm4(af[mt], base + (wm + mt * 16) * 144 + aoff + k8 * 32);
            uint32_t bf[2][4];
#pragma unroll
            for (int bt = 0; bt < 2; ++bt)
                ldsm4(bf[bt], base + ABYTES + (wn + bt * 16) * 144 + boff + k8 * 32);
#pragma unroll
            for (int mt = 0; mt < 4; ++mt) {
                mma8(acc[mt][0], af[mt], bf[0][0], bf[0][1]);
                mma8(acc[mt][1], af[mt], bf[0][2], bf[0][3]);
                mma8(acc[mt][2], af[mt], bf[1][0], bf[1][1]);
                mma8(acc[mt][3], af[mt], bf[1][2], bf[1][3]);
            }
        }
    }

#pragma unroll
    for (int mt = 0; mt < 4; ++mt) {
#pragma unroll
        for (int half = 0; half < 2; ++half) {
            int m = mbase + wm + mt * 16 + g + half * 8;
            float* dst = out + (size_t)token_src(m) * 256;
#pragma unroll
            for (int nt = 0; nt < 4; ++nt) {
                int n0 = nbase + wn + nt * 8 + tg * 2;
                float2 val;
                val.x = acc[mt][nt][half * 2 + 0] + __ldg(bout + n0);
                val.y = acc[mt][nt][half * 2 + 1] + __ldg(bout + n0 + 1);
                *(float2*)(dst + n0) = val;
            }
        }
    }
}

// ---------------------------------------------------------------------------
extern "C" void kernel_launch(void* const* d_in, const int* in_sizes, int n_in,
                              void* d_out, int out_size) {
    const float* x    = (const float*)d_in[0];
    const float* wqkv = (const float*)d_in[1];
    const float* bqkv = (const float*)d_in[2];
    const float* wout = (const float*)d_in[3];
    const float* bout = (const float*)d_in[4];
    const float* pos  = (const float*)d_in[5];
    float* out = (float*)d_out;

    const int smem = 3 * STAGE;  // 110592
    cudaFuncSetAttribute(k_qkv, cudaFuncAttributeMaxDynamicSharedMemorySize, smem);
    cudaFuncSetAttribute(k_out, cudaFuncAttributeMaxDynamicSharedMemorySize, smem);

    k_round<<<256, 256>>>(wqkv, wout);
    k_qkv<<<dim3(6, 1024), 256, smem>>>(x, bqkv);
    k_attn<<<16384, 128>>>(pos);
    k_out<<<dim3(2, 1024), 256, smem>>>(bout, out);
}

// round 11
// speedup vs baseline: 1.5263x; 1.5263x over previous
#include <cuda_runtime.h>
#include <cstdint>

// ---------------------------------------------------------------------------
// Swin shifted-window attention. B=32, 64x64, C=256, 8 heads x 32, ws=8, shift=4.
// Legacy tensor path only (harness PTX target sm_103 rejects tcgen05).
// k_round: pre-round w_qkv, w_out to tf32 (RNA)
// k_qkv  : qkv = gather(x) @ w_qkv^T + b ; 3-stage ring, frag double-buffer
// k_attn : per (window,head) attention; smem overlay (ps over qs/ks)
// k_out  : out = o @ w_out^T + b ; 3-stage ring, frag double-buffer, scatter
// ---------------------------------------------------------------------------

#define SCALE_F 0.1767766952966369f
#define ABYTES  18432               // 128*36*4 (one operand, one stage)
#define STAGE   36864               // A+B one stage

__device__ float g_wqkv[196608];    // rounded w_qkv
__device__ float g_wout[65536];     // rounded w_out
__device__ float g_q[33554432];     // [win][head][tok 64][d 32]
__device__ float g_k[33554432];     // [win][head][tok 64][d 32]
__device__ float g_v[33554432];     // [win][head][d 32][tok 64]  (transposed)
__device__ float g_o[33554432];     // [token 131072][256] rounded

__device__ __forceinline__ float tf32f(float f) {
    uint32_t u;
    asm("cvt.rna.tf32.f32 %0, %1;" : "=r"(u) : "f"(f));
    return __uint_as_float(u);
}
__device__ __forceinline__ uint32_t smem_u32(const void* p) {
    return (uint32_t)__cvta_generic_to_shared(p);
}
__device__ __forceinline__ void cp16(uint32_t s, const void* g) {
    asm volatile("cp.async.cg.shared.global [%0], [%1], 16;" :: "r"(s), "l"(g));
}
__device__ __forceinline__ void cp_commit() {
    asm volatile("cp.async.commit_group;");
}
template <int N> __device__ __forceinline__ void cp_wait() {
    asm volatile("cp.async.wait_group %0;" :: "n"(N));
}
__device__ __forceinline__ void ldsm4(uint32_t* r, uint32_t a) {
    asm volatile("ldmatrix.sync.aligned.m8n8.x4.shared.b16 {%0,%1,%2,%3}, [%4];"
                 : "=r"(r[0]), "=r"(r[1]), "=r"(r[2]), "=r"(r[3]) : "r"(a));
}
__device__ __forceinline__ void mma8(float* c, const uint32_t* a,
                                     uint32_t b0, uint32_t b1) {
    asm volatile("mma.sync.aligned.m16n8k8.row.col.f32.tf32.tf32.f32 "
                 "{%0,%1,%2,%3},{%4,%5,%6,%7},{%8,%9},{%0,%1,%2,%3};\n"
                 : "+f"(c[0]), "+f"(c[1]), "+f"(c[2]), "+f"(c[3])
                 : "r"(a[0]), "r"(a[1]), "r"(a[2]), "r"(a[3]), "r"(b0), "r"(b1));
}

// window-token m -> source row in (B,64,64), cyclic shift by 4 (self-inverse)
__device__ __forceinline__ int token_src(int m) {
    int w = m >> 6, p = m & 63;
    int b = w >> 6, widx = w & 63;
    int y = (((widx >> 3) << 3) + (p >> 3) + 4) & 63;
    int x = (((widx & 7) << 3) + (p & 7) + 4) & 63;
    return (b << 12) | (y << 6) | x;
}

// ---------------------------------------------------------------------------
__global__ void k_round(const float* __restrict__ wq, const float* __restrict__ wo) {
    const int NQ = 196608 / 4, NO = 65536 / 4;
    int i = blockIdx.x * blockDim.x + threadIdx.x;
    if (i < NQ + NO) {
        const float4* s;
        float4* d;
        if (i < NQ) { s = (const float4*)wq + i;        d = (float4*)g_wqkv + i; }
        else        { s = (const float4*)wo + (i - NQ); d = (float4*)g_wout + (i - NQ); }
        float4 v = __ldg(s);
        v.x = tf32f(v.x); v.y = tf32f(v.y); v.z = tf32f(v.z); v.w = tf32f(v.w);
        *d = v;
    }
}

// ---------------------------------------------------------------------------
// K1: qkv GEMM. CTA 128(M) x 128(N), K=256 in 8 chunks of 32.
// 3-stage ring + fragment double-buffer. 8 warps: 2(M,64) x 4(N,32).
// ---------------------------------------------------------------------------
__global__ void __launch_bounds__(256, 2)
k_qkv(const float* __restrict__ x, const float* __restrict__ bqkv) {
    extern __shared__ float smf[];
    const int t = threadIdx.x;
    const int mbase = blockIdx.y << 7;
    const int nbase = blockIdx.x << 7;
    const int lane = t & 31, wid = t >> 5;
    const int g = lane >> 2, tg = lane & 3;
    const int wm = (wid & 1) << 6;
    const int wn = (wid >> 1) << 5;

    const uint32_t sbase = smem_u32(smf);
    const int srow = t >> 1, scol = (t & 1) << 4;
    const float* gA = x + (size_t)token_src(mbase + srow) * 256 + scol;
    const float* gB = g_wqkv + (size_t)(nbase + srow) * 256 + scol;
    const uint32_t offA = (srow * 36 + scol) * 4;
    const uint32_t offB = offA + ABYTES;

    const int tt = lane >> 3, rr = lane & 7;
    const uint32_t aoff = (((tt & 1) * 8 + rr) * 36 + (tt >> 1) * 4) * 4;
    const uint32_t boff = (((tt >> 1) * 8 + rr) * 36 + (tt & 1) * 4) * 4;

    float acc[4][4][4] = {};

#pragma unroll
    for (int s = 0; s < 2; ++s) {
#pragma unroll
        for (int j = 0; j < 4; ++j) {
            float4 v = __ldg((const float4*)(gA + s * 32 + j * 4));
            v.x = tf32f(v.x); v.y = tf32f(v.y); v.z = tf32f(v.z); v.w = tf32f(v.w);
            *(float4*)((char*)smf + s * STAGE + offA + j * 16) = v;
        }
#pragma unroll
        for (int j = 0; j < 4; ++j)
            cp16(sbase + s * STAGE + offB + j * 16, gB + s * 32 + j * 4);
        cp_commit();
    }

    for (int kc = 0; kc < 8; ++kc) {
        if (kc == 7) cp_wait<0>(); else cp_wait<1>();
        __syncthreads();

        if (kc < 6) {
            const int s = kc + 2;
            const uint32_t sb = (uint32_t)(s % 3) * STAGE;
#pragma unroll
            for (int j = 0; j < 4; ++j) {
                float4 v = __ldg((const float4*)(gA + s * 32 + j * 4));
                v.x = tf32f(v.x); v.y = tf32f(v.y); v.z = tf32f(v.z); v.w = tf32f(v.w);
                *(float4*)((char*)smf + sb + offA + j * 16) = v;
            }
#pragma unroll
            for (int j = 0; j < 4; ++j)
                cp16(sbase + sb + offB + j * 16, gB + s * 32 + j * 4);
            cp_commit();
        }

        const uint32_t base = sbase + (uint32_t)(kc % 3) * STAGE;
        uint32_t af[2][4][4], bf[2][2][4];
#pragma unroll
        for (int mt = 0; mt < 4; ++mt)
            ldsm4(af[0][mt], base + (wm + mt * 16) * 144 + aoff);
#pragma unroll
        for (int bt = 0; bt < 2; ++bt)
            ldsm4(bf[0][bt], base + ABYTES + (wn + bt * 16) * 144 + boff);
#pragma unroll
        for (int k8 = 0; k8 < 4; ++k8) {
            const int cur = k8 & 1, nxt = cur ^ 1;
            if (k8 < 3) {
#pragma unroll
                for (int mt = 0; mt < 4; ++mt)
                    ldsm4(af[nxt][mt], base + (wm + mt * 16) * 144 + aoff + (k8 + 1) * 32);
#pragma unroll
                for (int bt = 0; bt < 2; ++bt)
                    ldsm4(bf[nxt][bt], base + ABYTES + (wn + bt * 16) * 144 + boff + (k8 + 1) * 32);
            }
#pragma unroll
            for (int mt = 0; mt < 4; ++mt) {
                mma8(acc[mt][0], af[cur][mt], bf[cur][0][0], bf[cur][0][1]);
                mma8(acc[mt][1], af[cur][mt], bf[cur][0][2], bf[cur][0][3]);
                mma8(acc[mt][2], af[cur][mt], bf[cur][1][0], bf[cur][1][1]);
                mma8(acc[mt][3], af[cur][mt], bf[cur][1][2], bf[cur][1][3]);
            }
        }
    }

    const int which = nbase >> 8;  // uniform per CTA: 0=q, 1=k, 2=v
#pragma unroll
    for (int mt = 0; mt < 4; ++mt) {
#pragma unroll
        for (int half = 0; half < 2; ++half) {
            int m = mbase + wm + mt * 16 + g + half * 8;
            int w = m >> 6, p = m & 63;
#pragma unroll
            for (int nt = 0; nt < 4; ++nt) {
                int n0 = nbase + wn + nt * 8 + tg * 2;
                int h = (n0 >> 5) & 7, d = n0 & 31;
                int wh = (w << 3) + h;
                float v0 = tf32f(acc[mt][nt][half * 2 + 0] + __ldg(bqkv + n0));
                float v1 = tf32f(acc[mt][nt][half * 2 + 1] + __ldg(bqkv + n0 + 1));
                if (which == 0) {
                    *(float2*)(g_q + ((wh << 6) + p) * 32 + d) = make_float2(v0, v1);
                } else if (which == 1) {
                    *(float2*)(g_k + ((wh << 6) + p) * 32 + d) = make_float2(v0, v1);
                } else {
                    g_v[(((wh << 5) + d) << 6) + p] = v0;
                    g_v[(((wh << 5) + d + 1) << 6) + p] = v1;
                }
            }
        }
    }
}

// ---------------------------------------------------------------------------
// K2: attention per (window, head). 4 warps; ps overlays qs/ks (smem 27.4KB).
// ---------------------------------------------------------------------------
__global__ void __launch_bounds__(128)
k_attn(const float* __restrict__ pos_enc) {
    __shared__ float smraw[7016];        // 28,064 bytes total
    float* qs    = smraw;                // 64*36 = 2304
    float* ks    = smraw + 2304;         // 64*36 = 2304
    float* vs    = smraw + 4608;         // 32*68 = 2176
    float* pos_s = smraw + 6784;         // 232
    float* ps    = smraw;                // overlay: 64*68 = 4352 <= 4608 (qs+ks)

    const int t = threadIdx.x;
    const int bh = blockIdx.x;
    const int w = bh >> 3, h = bh & 7;
    const int wh = (w << 3) + h;

    {
        int row = t >> 1, col = (t & 1) << 4;
        const float* q = g_q + ((size_t)(wh << 6) + row) * 32 + col;
        const float* k = g_k + ((size_t)(wh << 6) + row) * 32 + col;
        uint32_t dq = smem_u32(qs) + (row * 36 + col) * 4;
        uint32_t dk = smem_u32(ks) + (row * 36 + col) * 4;
#pragma unroll
        for (int j = 0; j < 4; ++j) { cp16(dq + j * 16, q + j * 4); cp16(dk + j * 16, k + j * 4); }
        int vr = t >> 2, vc = (t & 3) << 4;
        const float* v = g_v + ((size_t)(wh << 5) + vr) * 64 + vc;
        uint32_t dv = smem_u32(vs) + (vr * 68 + vc) * 4;
#pragma unroll
        for (int j = 0; j < 4; ++j) { cp16(dv + j * 16, v + j * 4); }
        cp_commit();
    }
    for (int i = t; i < 225; i += 128) pos_s[i] = __ldg(pos_enc + h * 225 + i);
    cp_wait<0>();
    __syncthreads();

    const int lane = t & 31, wid = t >> 5;
    const int g = lane >> 2, tg = lane & 3;
    const int wb = wid << 4;
    const int tt = lane >> 3, rr = lane & 7;
    const uint32_t aoff36 = (((tt & 1) * 8 + rr) * 36 + (tt >> 1) * 4) * 4;
    const uint32_t boff36 = (((tt >> 1) * 8 + rr) * 36 + (tt & 1) * 4) * 4;
    const uint32_t aoff68 = (((tt & 1) * 8 + rr) * 68 + (tt >> 1) * 4) * 4;
    const uint32_t boff68 = (((tt >> 1) * 8 + rr) * 68 + (tt & 1) * 4) * 4;

    // S = q k^T
    float sacc[8][4] = {};
    const uint32_t qb = smem_u32(qs) + wb * 144 + aoff36;
    const uint32_t kb = smem_u32(ks) + boff36;
#pragma unroll
    for (int k8 = 0; k8 < 4; ++k8) {
        uint32_t af[4];
        ldsm4(af, qb + k8 * 32);
        uint32_t bf[4][4];
#pragma unroll
        for (int bt = 0; bt < 4; ++bt)
            ldsm4(bf[bt], kb + bt * 16 * 144 + k8 * 32);
#pragma unroll
        for (int nt = 0; nt < 8; ++nt)
            mma8(sacc[nt], af, bf[nt >> 1][(nt & 1) * 2], bf[nt >> 1][(nt & 1) * 2 + 1]);
    }
    __syncthreads();  // all warps done reading qs/ks before ps overlay writes

    // bias + shift mask + softmax
    const int widx = w & 63;
    const int my = ((widx >> 3) == 7);
    const int mxw = ((widx & 7) == 7);
    auto regf = [&](int py, int px) {
        int ry = my ? (py < 4 ? 1 : 2) : 0;
        int rx = mxw ? (px < 4 ? 1 : 2) : 0;
        return ry * 3 + rx;
    };
    const int iL = wb + g, iH = iL + 8;
    const int pyL = iL >> 3, pxL = iL & 7;
    const int pyH = iH >> 3, pxH = iH & 7;
    const int regL = regf(pyL, pxL), regH = regf(pyH, pxH);

    float mL = -1e30f, mH = -1e30f;
#pragma unroll
    for (int nt = 0; nt < 8; ++nt) {
#pragma unroll
        for (int jj = 0; jj < 2; ++jj) {
            int j = (nt << 3) + (tg << 1) + jj;
            int pyj = j >> 3, pxj = j & 7;
            int regj = regf(pyj, pxj);
            float sL = sacc[nt][jj] * SCALE_F + pos_s[(pyL - pyj + 7) * 15 + (pxL - pxj + 7)];
            float sH = sacc[nt][2 + jj] * SCALE_F + pos_s[(pyH - pyj + 7) * 15 + (pxH - pxj + 7)];
            if (regj != regL) sL = -1e30f;
            if (regj != regH) sH = -1e30f;
            sacc[nt][jj] = sL;
            sacc[nt][2 + jj] = sH;
            mL = fmaxf(mL, sL);
            mH = fmaxf(mH, sH);
        }
    }
    mL = fmaxf(mL, __shfl_xor_sync(0xffffffffu, mL, 1));
    mL = fmaxf(mL, __shfl_xor_sync(0xffffffffu, mL, 2));
    mH = fmaxf(mH, __shfl_xor_sync(0xffffffffu, mH, 1));
    mH = fmaxf(mH, __shfl_xor_sync(0xffffffffu, mH, 2));

    float sumL = 0.f, sumH = 0.f;
#pragma unroll
    for (int nt = 0; nt < 8; ++nt) {
#pragma unroll
        for (int jj = 0; jj < 2; ++jj) {
            int j = (nt << 3) + (tg << 1) + jj;
            float eL = tf32f(__expf(sacc[nt][jj] - mL));
            float eH = tf32f(__expf(sacc[nt][2 + jj] - mH));
            sumL += eL;
            sumH += eH;
            ps[iL * 68 + j] = eL;
            ps[iH * 68 + j] = eH;
        }
    }
    sumL += __shfl_xor_sync(0xffffffffu, sumL, 1);
    sumL += __shfl_xor_sync(0xffffffffu, sumL, 2);
    sumH += __shfl_xor_sync(0xffffffffu, sumH, 1);
    sumH += __shfl_xor_sync(0xffffffffu, sumH, 2);
    const float invL = 1.f / sumL, invH = 1.f / sumH;
    __syncwarp();

    // O = P V  (warp reads only its own 16 ps rows, written by itself)
    float oacc[4][4] = {};
    const uint32_t pb = smem_u32(ps) + wb * 272 + aoff68;
    const uint32_t vb = smem_u32(vs) + boff68;
#pragma unroll
    for (int k8 = 0; k8 < 8; ++k8) {
        uint32_t pf[4];
        ldsm4(pf, pb + k8 * 32);
        uint32_t vf[2][4];
#pragma unroll
        for (int bt = 0; bt < 2; ++bt)
            ldsm4(vf[bt], vb + bt * 16 * 272 + k8 * 32);
#pragma unroll
        for (int nt = 0; nt < 4; ++nt)
            mma8(oacc[nt], pf, vf[nt >> 1][(nt & 1) * 2], vf[nt >> 1][(nt & 1) * 2 + 1]);
    }

    float* ob = g_o + (size_t)(w << 6) * 256 + (h << 5);
#pragma unroll
    for (int nt = 0; nt < 4; ++nt) {
        int d = (nt << 3) + (tg << 1);
        *(float2*)(ob + (size_t)iL * 256 + d) =
            make_float2(tf32f(oacc[nt][0] * invL), tf32f(oacc[nt][1] * invL));
        *(float2*)(ob + (size_t)iH * 256 + d) =
            make_float2(tf32f(oacc[nt][2] * invH), tf32f(oacc[nt][3] * invH));
    }
}

// ---------------------------------------------------------------------------
// K3: out = o @ w_out^T + b_out, 3-stage ring + frag double-buffer, scatter.
// ---------------------------------------------------------------------------
__global__ void __launch_bounds__(256, 2)
k_out(const float* __restrict__ bout, float* __restrict__ out) {
    extern __shared__ float smf[];
    const int t = threadIdx.x;
    const int mbase = blockIdx.y << 7;
    const int nbase = blockIdx.x << 7;
    const int lane = t & 31, wid = t >> 5;
    const int g = lane >> 2, tg = lane & 3;
    const int wm = (wid & 1) << 6;
    const int wn = (wid >> 1) << 5;

    const uint32_t sbase = smem_u32(smf);
    const int srow = t >> 1, scol = (t & 1) << 4;
    const float* gA = g_o + (size_t)(mbase + srow) * 256 + scol;
    const float* gB = g_wout + (size_t)(nbase + srow) * 256 + scol;
    const uint32_t offA = (srow * 36 + scol) * 4;
    const uint32_t offB = offA + ABYTES;

    const int tt = lane >> 3, rr = lane & 7;
    const uint32_t aoff = (((tt & 1) * 8 + rr) * 36 + (tt >> 1) * 4) * 4;
    const uint32_t boff = (((tt >> 1) * 8 + rr) * 36 + (tt & 1) * 4) * 4;

    float acc[4][4][4] = {};

#pragma unroll
    for (int s = 0; s < 2; ++s) {
        const uint32_t sb = sbase + s * STAGE;
#pragma unroll
        for (int j = 0; j < 4; ++j) {
            cp16(sb + offA + j * 16, gA + s * 32 + j * 4);
            cp16(sb + offB + j * 16, gB + s * 32 + j * 4);
        }
        cp_commit();
    }

    for (int kc = 0; kc < 8; ++kc) {
        if (kc == 7) cp_wait<0>(); else cp_wait<1>();
        __syncthreads();

        if (kc < 6) {
            const int s = kc + 2;
            const uint32_t sb = sbase + (uint32_t)(s % 3) * STAGE;
#pragma unroll
            for (int j = 0; j < 4; ++j) {
                cp16(sb + offA + j * 16, gA + s * 32 + j * 4);
                cp16(sb + offB + j * 16, gB + s * 32 + j * 4);
            }
            cp_commit();
        }

        const uint32_t base = sbase + (uint32_t)(kc % 3) * STAGE;
        uint32_t af[2][4][4], bf[2][2][4];
#pragma unroll
        for (int mt = 0; mt < 4; ++mt)
            ldsm4(af[0][mt], base + (wm + mt * 16) * 144 + aoff);
#pragma unroll
        for (int bt = 0; bt < 2; ++bt)
            ldsm4(bf[0][bt], base + ABYTES + (wn + bt * 16) * 144 + boff);
#pragma unroll
        for (int k8 = 0; k8 < 4; ++k8) {
            const int cur = k8 & 1, nxt = cur ^ 1;
            if (k8 < 3) {
#pragma unroll
                for (int mt = 0; mt < 4; ++mt)
                    ldsm4(af[nxt][mt], base + (wm + mt * 16) * 144 + aoff + (k8 + 1) * 32);
#pragma unroll
                for (int bt = 0; bt < 2; ++bt)
                    ldsm4(bf[nxt][bt], base + ABYTES + (wn + bt * 16) * 144 + boff + (k8 + 1) * 32);
            }
#pragma unroll
            for (int mt = 0; mt < 4; ++mt) {
                mma8(acc[mt][0], af[cur][mt], bf[cur][0][0], bf[cur][0][1]);
                mma8(acc[mt][1], af[cur][mt], bf[cur][0][2], bf[cur][0][3]);
                mma8(acc[mt][2], af[cur][mt], bf[cur][1][0], bf[cur][1][1]);
                mma8(acc[mt][3], af[cur][mt], bf[cur][1][2], bf[cur][1][3]);
            }
        }
    }

#pragma unroll
    for (int mt = 0; mt < 4; ++mt) {
#pragma unroll
        for (int half = 0; half < 2; ++half) {
            int m = mbase + wm + mt * 16 + g + half * 8;
            float* dst = out + (size_t)token_src(m) * 256;
#pragma unroll
            for (int nt = 0; nt < 4; ++nt) {
                int n0 = nbase + wn + nt * 8 + tg * 2;
                float2 val;
                val.x = acc[mt][nt][half * 2 + 0] + __ldg(bout + n0);
                val.y = acc[mt][nt][half * 2 + 1] + __ldg(bout + n0 + 1);
                *(float2*)(dst + n0) = val;
            }
        }
    }
}

// ---------------------------------------------------------------------------
extern "C" void kernel_launch(void* const* d_in, const int* in_sizes, int n_in,
                              void* d_out, int out_size) {
    const float* x    = (const float*)d_in[0];
    const float* wqkv = (const float*)d_in[1];
    const float* bqkv = (const float*)d_in[2];
    const float* wout = (const float*)d_in[3];
    const float* bout = (const float*)d_in[4];
    const float* pos  = (const float*)d_in[5];
    float* out = (float*)d_out;

    const int smem = 3 * STAGE;  // 110592
    cudaFuncSetAttribute(k_qkv, cudaFuncAttributeMaxDynamicSharedMemorySize, smem);
    cudaFuncSetAttribute(k_out, cudaFuncAttributeMaxDynamicSharedMemorySize, smem);

    k_round<<<256, 256>>>(wqkv, wout);
    k_qkv<<<dim3(6, 1024), 256, smem>>>(x, bqkv);
    k_attn<<<16384, 128>>>(pos);
    k_out<<<dim3(2, 1024), 256, smem>>>(bout, out);
}